// round 16
// baseline (speedup 1.0000x reference)
#include <cuda_runtime.h>
#include <cstdint>

// Problem constants
#define BB 4
#define SS 1024
#define DD 1024
#define HH 16
#define HD 64
#define N3D 3072          // 3*D
#define MM (BB*SS)        // 4096 rows of the GEMM

// Head-major scratch for Q/K/V: [B,H,S,HD]; pre-rounded (tf32) copies of x and W
__device__ float g_q[BB*HH*SS*HD];
__device__ float g_k[BB*HH*SS*HD];
__device__ float g_v[BB*HH*SS*HD];
__device__ float g_xr[MM*DD];
__device__ float g_wr[DD*N3D];

// ---------------------------------------------------------------------------
// Helpers
// ---------------------------------------------------------------------------
__device__ __forceinline__ uint32_t f2tf32(float x) {
    uint32_t y;
    asm volatile("cvt.rna.tf32.f32 %0, %1;" : "=r"(y) : "f"(x));
    return y;
}
__device__ __forceinline__ float f2tf32f(float x) {
    return __uint_as_float(f2tf32(x));
}
__device__ __forceinline__ uint32_t smem_u32(const void* p) {
    uint32_t a;
    asm("{ .reg .u64 t; cvta.to.shared.u64 t, %1; cvt.u32.u64 %0, t; }" : "=r"(a) : "l"(p));
    return a;
}
__device__ __forceinline__ void cpasync16(uint32_t dst, const float* src) {
    asm volatile("cp.async.cg.shared.global [%0], [%1], 16;" :: "r"(dst), "l"(src));
}
__device__ __forceinline__ void mma_tf32(float& c0, float& c1, float& c2, float& c3,
                                         uint32_t a0, uint32_t a1, uint32_t a2, uint32_t a3,
                                         uint32_t b0, uint32_t b1) {
    asm volatile(
        "mma.sync.aligned.m16n8k8.row.col.f32.tf32.tf32.f32 "
        "{%0,%1,%2,%3}, {%4,%5,%6,%7}, {%8,%9}, {%0,%1,%2,%3};"
        : "+f"(c0), "+f"(c1), "+f"(c2), "+f"(c3)
        : "r"(a0), "r"(a1), "r"(a2), "r"(a3), "r"(b0), "r"(b1));
}

// ---------------------------------------------------------------------------
// Kernel 0: pre-round x and W to tf32 (RNA) stored as fp32 bit patterns.
// ---------------------------------------------------------------------------
__global__ void preround_kernel(const float* __restrict__ x,
                                const float* __restrict__ W) {
    int i = blockIdx.x * blockDim.x + threadIdx.x;   // float4 index
    if (i < MM * DD / 4) {
        float4 v = reinterpret_cast<const float4*>(x)[i];
        uint4 r;
        r.x = f2tf32(v.x); r.y = f2tf32(v.y);
        r.z = f2tf32(v.z); r.w = f2tf32(v.w);
        reinterpret_cast<uint4*>(g_xr)[i] = r;
    }
    if (i < DD * N3D / 4) {
        float4 v = reinterpret_cast<const float4*>(W)[i];
        uint4 r;
        r.x = f2tf32(v.x); r.y = f2tf32(v.y);
        r.z = f2tf32(v.z); r.w = f2tf32(v.w);
        reinterpret_cast<uint4*>(g_wr)[i] = r;
    }
}

// ---------------------------------------------------------------------------
// Kernel 1: qkv = xr @ wr + b via TF32 mma.sync, cp.async double-buffered.
// (unchanged from round 13/14 — measured ~170us)
// ---------------------------------------------------------------------------
__global__ __launch_bounds__(256, 2)
void qkv_mma_kernel(const float* __restrict__ bias) {
    __shared__ __align__(16) float sA[2][128 * 16];
    __shared__ __align__(16) float sB[2][16 * 128];

    const int tid  = threadIdx.x;
    const int lane = tid & 31;
    const int warp = tid >> 5;
    const int gid  = lane >> 2;
    const int tig  = lane & 3;
    const int warpM = (warp >> 2) * 64;
    const int warpN = (warp & 3) * 32;
    const int tileM = blockIdx.y * 128;
    const int tileN = blockIdx.x * 128;

    const int a_m0 = tid >> 2;
    const int a_kc = (tid & 3) * 4;
    const int b_k0 = tid >> 5;
    const int b_nc = (tid & 31) * 4;

    const uint32_t sAb = smem_u32(&sA[0][0]);
    const uint32_t sBb = smem_u32(&sB[0][0]);

    float acc[4][4][4];
#pragma unroll
    for (int mi = 0; mi < 4; mi++)
#pragma unroll
        for (int ni = 0; ni < 4; ni++)
#pragma unroll
            for (int c = 0; c < 4; c++) acc[mi][ni][c] = 0.0f;

#define ISSUE_TILE(t, s) do {                                                        \
        int _k0 = (t) * 16;                                                          \
        _Pragma("unroll")                                                            \
        for (int _i = 0; _i < 2; _i++) {                                             \
            int _m = a_m0 + _i * 64;                                                 \
            uint32_t _d = sAb + (uint32_t)((s) * 8192 +                              \
                          (_m * 16 + (a_kc ^ (4 * ((_m >> 1) & 3)))) * 4);           \
            cpasync16(_d, &g_xr[(size_t)(tileM + _m) * DD + _k0 + a_kc]);            \
        }                                                                            \
        _Pragma("unroll")                                                            \
        for (int _i = 0; _i < 2; _i++) {                                             \
            int _k = b_k0 + _i * 8;                                                  \
            uint32_t _d = sBb + (uint32_t)((s) * 8192 +                              \
                          (_k * 128 + (b_nc ^ (8 * (_k & 3)))) * 4);                 \
            cpasync16(_d, &g_wr[(size_t)(_k0 + _k) * N3D + tileN + b_nc]);           \
        }                                                                            \
        asm volatile("cp.async.commit_group;" ::: "memory");                         \
    } while (0)

    ISSUE_TILE(0, 0);

    const int swzA = 4 * ((gid >> 1) & 3);
    const int NT = DD / 16;
    for (int t = 0; t < NT; t++) {
        if (t + 1 < NT) {
            ISSUE_TILE(t + 1, (t + 1) & 1);
            asm volatile("cp.async.wait_group 1;" ::: "memory");
        } else {
            asm volatile("cp.async.wait_group 0;" ::: "memory");
        }
        __syncthreads();

        const float* A  = &sA[t & 1][0];
        const float* Bt = &sB[t & 1][0];
#pragma unroll
        for (int ks = 0; ks < 16; ks += 8) {
            uint32_t af[4][4];
            uint32_t bf[4][2];
#pragma unroll
            for (int mi = 0; mi < 4; mi++) {
                int m0 = warpM + mi * 16 + gid;
                int kA = ks + tig;
                af[mi][0] = __float_as_uint(A[m0 * 16       + (kA ^ swzA)]);
                af[mi][1] = __float_as_uint(A[(m0 + 8) * 16 + (kA ^ swzA)]);
                af[mi][2] = __float_as_uint(A[m0 * 16       + ((kA + 4) ^ swzA)]);
                af[mi][3] = __float_as_uint(A[(m0 + 8) * 16 + ((kA + 4) ^ swzA)]);
            }
#pragma unroll
            for (int ni = 0; ni < 4; ni++) {
                int n0 = warpN + ni * 8 + gid;
                bf[ni][0] = __float_as_uint(Bt[(ks + tig) * 128     + (n0 ^ (8 * tig))]);
                bf[ni][1] = __float_as_uint(Bt[(ks + tig + 4) * 128 + (n0 ^ (8 * tig))]);
            }
#pragma unroll
            for (int mi = 0; mi < 4; mi++)
#pragma unroll
                for (int ni = 0; ni < 4; ni++)
                    mma_tf32(acc[mi][ni][0], acc[mi][ni][1], acc[mi][ni][2], acc[mi][ni][3],
                             af[mi][0], af[mi][1], af[mi][2], af[mi][3],
                             bf[ni][0], bf[ni][1]);
        }
        __syncthreads();
    }
#undef ISSUE_TILE

#pragma unroll
    for (int mi = 0; mi < 4; mi++) {
#pragma unroll
        for (int ni = 0; ni < 4; ni++) {
            int row0 = tileM + warpM + mi * 16 + gid;
            int col0 = tileN + warpN + ni * 8 + tig * 2;
#pragma unroll
            for (int c = 0; c < 4; c++) {
                int m   = row0 + (c >> 1) * 8;
                int col = col0 + (c & 1);
                float val = acc[mi][ni][c] + bias[col];
                int b = m >> 10;
                int s = m & 1023;
                int h  = col / 192;
                int cc = col - h * 192;
                size_t base = ((size_t)(b * HH + h) * SS + s) * HD;
                if (cc < 64)       g_q[base + cc]       = val * 0.125f;
                else if (cc < 128) g_k[base + cc - 64]  = val;
                else               g_v[base + cc - 128] = val;
            }
        }
    }
}

// ---------------------------------------------------------------------------
// Kernel 2: flash-attention via TF32 mma.sync.
// Block = one (b,h) x 128 q-rows; 8 warps x 16 q-rows. 16 key tiles of 64.
// Dynamic smem 64KB: SP[128x64] (Qs then Ps), Ks[64x64], Vs[64x64].
//   SP: swizzle col ^ 4*(q&7); Ks: d ^ 4*(key&7); Vs: d ^ 8*(key&3)
// ALL tf32 operands RNA-rounded at staging (removes truncation bias).
// Scores/O in registers; online softmax; Ps warp-private rows.
// ---------------------------------------------------------------------------
__global__ __launch_bounds__(256)
void attn_mma_kernel(float* __restrict__ out) {
    extern __shared__ __align__(16) float dsm[];
    float* SP = dsm;                 // 128*64 floats (32KB)
    float* Ks = dsm + 128 * 64;      // 64*64 (16KB)
    float* Vs = Ks + 64 * 64;        // 64*64 (16KB)

    const int tid  = threadIdx.x;
    const int lane = tid & 31;
    const int warp = tid >> 5;       // 0..7
    const int gid  = lane >> 2;      // 0..7
    const int tig  = lane & 3;       // 0..3
    const int m0   = warp * 16;
    const int bh   = blockIdx.x;     // 0..63
    const int q0   = blockIdx.y * 128;
    const int xq   = 4 * gid;

    const int sj = tid & 15;         // float4 within 64-float row
    const int sr = tid >> 4;         // 0..15

    // Stage Q (128 rows, swizzled, RNA-rounded)
#pragma unroll
    for (int p = 0; p < 8; p++) {
        int row = sr + 16 * p;
        float4 qv = *reinterpret_cast<const float4*>(
            &g_q[((size_t)bh * SS + q0 + row) * HD + 4 * sj]);
        qv.x = f2tf32f(qv.x); qv.y = f2tf32f(qv.y);
        qv.z = f2tf32f(qv.z); qv.w = f2tf32f(qv.w);
        *reinterpret_cast<float4*>(&SP[row * 64 + ((4 * sj) ^ (4 * (row & 7)))]) = qv;
    }
    __syncthreads();

    // Q fragments for all 8 k-steps (warp-private rows of SP)
    uint32_t qf[8][4];
#pragma unroll
    for (int k8 = 0; k8 < 8; k8++) {
        int kk = k8 * 8;
        qf[k8][0] = __float_as_uint(SP[(m0 + gid) * 64     + ((kk + tig)     ^ xq)]);
        qf[k8][1] = __float_as_uint(SP[(m0 + gid + 8) * 64 + ((kk + tig)     ^ xq)]);
        qf[k8][2] = __float_as_uint(SP[(m0 + gid) * 64     + ((kk + tig + 4) ^ xq)]);
        qf[k8][3] = __float_as_uint(SP[(m0 + gid + 8) * 64 + ((kk + tig + 4) ^ xq)]);
    }

    float O[8][4];
#pragma unroll
    for (int nt = 0; nt < 8; nt++)
#pragma unroll
        for (int c = 0; c < 4; c++) O[nt][c] = 0.0f;
    float mA = -1e30f, mB = -1e30f, lA = 0.0f, lB = 0.0f;

    for (int kt = 0; kt < 16; kt++) {
        __syncthreads();   // prev PV done (and q-frags loaded, first iter)
        // Stage K and V tiles (64 rows, swizzled, RNA-rounded)
#pragma unroll
        for (int p = 0; p < 4; p++) {
            int row = sr + 16 * p;
            size_t gb = ((size_t)bh * SS + kt * 64 + row) * HD + 4 * sj;
            float4 kv = *reinterpret_cast<const float4*>(&g_k[gb]);
            float4 vv = *reinterpret_cast<const float4*>(&g_v[gb]);
            kv.x = f2tf32f(kv.x); kv.y = f2tf32f(kv.y);
            kv.z = f2tf32f(kv.z); kv.w = f2tf32f(kv.w);
            vv.x = f2tf32f(vv.x); vv.y = f2tf32f(vv.y);
            vv.z = f2tf32f(vv.z); vv.w = f2tf32f(vv.w);
            *reinterpret_cast<float4*>(&Ks[row * 64 + ((4 * sj) ^ (4 * (row & 7)))]) = kv;
            *reinterpret_cast<float4*>(&Vs[row * 64 + ((4 * sj) ^ (8 * (row & 3)))]) = vv;
        }
        __syncthreads();

        // --- S = Q @ K^T : B[k=d][n=key] = Ks[key][d] ---
        float sc[8][4];
#pragma unroll
        for (int nt = 0; nt < 8; nt++)
#pragma unroll
            for (int c = 0; c < 4; c++) sc[nt][c] = 0.0f;
#pragma unroll
        for (int k8 = 0; k8 < 8; k8++) {
            int kk = k8 * 8;
#pragma unroll
            for (int nt = 0; nt < 8; nt++) {
                int n0 = nt * 8;
                uint32_t b0 = __float_as_uint(Ks[(n0 + gid) * 64 + ((kk + tig)     ^ xq)]);
                uint32_t b1 = __float_as_uint(Ks[(n0 + gid) * 64 + ((kk + tig + 4) ^ xq)]);
                mma_tf32(sc[nt][0], sc[nt][1], sc[nt][2], sc[nt][3],
                         qf[k8][0], qf[k8][1], qf[k8][2], qf[k8][3], b0, b1);
            }
        }

        // --- online softmax (rows A=gid, B=gid+8) ---
        float tA = -1e30f, tB = -1e30f;
#pragma unroll
        for (int nt = 0; nt < 8; nt++) {
            tA = fmaxf(tA, fmaxf(sc[nt][0], sc[nt][1]));
            tB = fmaxf(tB, fmaxf(sc[nt][2], sc[nt][3]));
        }
        tA = fmaxf(tA, __shfl_xor_sync(0xffffffffu, tA, 1));
        tA = fmaxf(tA, __shfl_xor_sync(0xffffffffu, tA, 2));
        tB = fmaxf(tB, __shfl_xor_sync(0xffffffffu, tB, 1));
        tB = fmaxf(tB, __shfl_xor_sync(0xffffffffu, tB, 2));
        float mnA = fmaxf(mA, tA), mnB = fmaxf(mB, tB);
        float cA = __expf(mA - mnA), cB = __expf(mB - mnB);
        mA = mnA; mB = mnB;

        float psA = 0.0f, psB = 0.0f;
#pragma unroll
        for (int nt = 0; nt < 8; nt++) {
            float p0 = __expf(sc[nt][0] - mA);
            float p1 = __expf(sc[nt][1] - mA);
            float p2 = __expf(sc[nt][2] - mB);
            float p3 = __expf(sc[nt][3] - mB);
            psA += p0 + p1; psB += p2 + p3;
            int colw = (nt * 8 + 2 * tig) ^ xq;   // XOR(mult of 4) keeps float2 aligned
            *reinterpret_cast<float2*>(&SP[(m0 + gid) * 64 + colw]) =
                make_float2(f2tf32f(p0), f2tf32f(p1));
            *reinterpret_cast<float2*>(&SP[(m0 + gid + 8) * 64 + colw]) =
                make_float2(f2tf32f(p2), f2tf32f(p3));
            O[nt][0] *= cA; O[nt][1] *= cA; O[nt][2] *= cB; O[nt][3] *= cB;
        }
        psA += __shfl_xor_sync(0xffffffffu, psA, 1);
        psA += __shfl_xor_sync(0xffffffffu, psA, 2);
        psB += __shfl_xor_sync(0xffffffffu, psB, 1);
        psB += __shfl_xor_sync(0xffffffffu, psB, 2);
        lA = lA * cA + psA;
        lB = lB * cB + psB;
        __syncwarp();   // Ps visible to all lanes of this warp

        // --- O += P @ V : A = Ps (warp-private rows), B[k=key][n=d] = Vs ---
#pragma unroll
        for (int k8 = 0; k8 < 8; k8++) {
            int kk = k8 * 8;
            uint32_t a0 = __float_as_uint(SP[(m0 + gid) * 64     + ((kk + tig)     ^ xq)]);
            uint32_t a1 = __float_as_uint(SP[(m0 + gid + 8) * 64 + ((kk + tig)     ^ xq)]);
            uint32_t a2 = __float_as_uint(SP[(m0 + gid) * 64     + ((kk + tig + 4) ^ xq)]);
            uint32_t a3 = __float_as_uint(SP[(m0 + gid + 8) * 64 + ((kk + tig + 4) ^ xq)]);
#pragma unroll
            for (int nt = 0; nt < 8; nt++) {
                uint32_t b0 = __float_as_uint(Vs[(kk + tig) * 64     + ((nt * 8 + gid) ^ (8 * tig))]);
                uint32_t b1 = __float_as_uint(Vs[(kk + tig + 4) * 64 + ((nt * 8 + gid) ^ (8 * tig))]);
                mma_tf32(O[nt][0], O[nt][1], O[nt][2], O[nt][3], a0, a1, a2, a3, b0, b1);
            }
        }
    }

    // Epilogue: out[b, q, h*64 + d]
    const int b = bh >> 4;
    const int h = bh & 15;
    float iA = 1.0f / lA, iB = 1.0f / lB;
    size_t rowA = ((size_t)b * SS + q0 + m0 + gid) * DD + h * HD;
    size_t rowB = rowA + (size_t)8 * DD;
#pragma unroll
    for (int nt = 0; nt < 8; nt++) {
        int col = nt * 8 + 2 * tig;
        *reinterpret_cast<float2*>(&out[rowA + col]) = make_float2(O[nt][0] * iA, O[nt][1] * iA);
        *reinterpret_cast<float2*>(&out[rowB + col]) = make_float2(O[nt][2] * iB, O[nt][3] * iB);
    }
}

extern "C" void kernel_launch(void* const* d_in, const int* in_sizes, int n_in,
                              void* d_out, int out_size) {
    const float* x  = (const float*)d_in[0];   // [B,S,D]
    const float* Wq = (const float*)d_in[1];   // [D,3D]
    const float* bq = (const float*)d_in[2];   // [3D]
    float* out      = (float*)d_out;           // [B,S,D]

    int np = MM * DD / 4;
    preround_kernel<<<(np + 255) / 256, 256>>>(x, Wq);

    dim3 gridG(N3D / 128, MM / 128);           // (24, 32)
    qkv_mma_kernel<<<gridG, 256>>>(bq);

    const int attn_smem = (128 * 64 + 64 * 64 + 64 * 64) * 4;   // 65536
    cudaFuncSetAttribute(attn_mma_kernel,
                         cudaFuncAttributeMaxDynamicSharedMemorySize, attn_smem);
    dim3 gridA(BB * HH, SS / 128);             // (64, 8)
    attn_mma_kernel<<<gridA, 256, attn_smem>>>(out);
}

// round 17
// speedup vs baseline: 1.6532x; 1.6532x over previous
#include <cuda_runtime.h>
#include <cstdint>

// Problem constants
#define BB 4
#define SS 1024
#define DD 1024
#define HH 16
#define HD 64
#define N3D 3072          // 3*D
#define MM (BB*SS)        // 4096 rows of the GEMM

// Head-major scratch for Q/K/V (tf32-rounded at write): [B,H,S,HD]
// Pre-rounded (tf32) copies of x and W for the GEMM.
__device__ float g_q[BB*HH*SS*HD];
__device__ float g_k[BB*HH*SS*HD];
__device__ float g_v[BB*HH*SS*HD];
__device__ float g_xr[MM*DD];
__device__ float g_wr[DD*N3D];

// ---------------------------------------------------------------------------
// Helpers
// ---------------------------------------------------------------------------
__device__ __forceinline__ uint32_t f2tf32(float x) {
    uint32_t y;
    asm volatile("cvt.rna.tf32.f32 %0, %1;" : "=r"(y) : "f"(x));
    return y;
}
__device__ __forceinline__ float f2tf32f(float x) {
    return __uint_as_float(f2tf32(x));
}
__device__ __forceinline__ uint32_t smem_u32(const void* p) {
    uint32_t a;
    asm("{ .reg .u64 t; cvta.to.shared.u64 t, %1; cvt.u32.u64 %0, t; }" : "=r"(a) : "l"(p));
    return a;
}
__device__ __forceinline__ void cpasync16(uint32_t dst, const float* src) {
    asm volatile("cp.async.cg.shared.global [%0], [%1], 16;" :: "r"(dst), "l"(src));
}
__device__ __forceinline__ void mma_tf32(float& c0, float& c1, float& c2, float& c3,
                                         uint32_t a0, uint32_t a1, uint32_t a2, uint32_t a3,
                                         uint32_t b0, uint32_t b1) {
    asm volatile(
        "mma.sync.aligned.m16n8k8.row.col.f32.tf32.tf32.f32 "
        "{%0,%1,%2,%3}, {%4,%5,%6,%7}, {%8,%9}, {%0,%1,%2,%3};"
        : "+f"(c0), "+f"(c1), "+f"(c2), "+f"(c3)
        : "r"(a0), "r"(a1), "r"(a2), "r"(a3), "r"(b0), "r"(b1));
}

// ---------------------------------------------------------------------------
// Kernel 0: pre-round x and W to tf32 (RNA) stored as fp32 bit patterns.
// ---------------------------------------------------------------------------
__global__ void preround_kernel(const float* __restrict__ x,
                                const float* __restrict__ W) {
    int i = blockIdx.x * blockDim.x + threadIdx.x;   // float4 index
    if (i < MM * DD / 4) {
        float4 v = reinterpret_cast<const float4*>(x)[i];
        uint4 r;
        r.x = f2tf32(v.x); r.y = f2tf32(v.y);
        r.z = f2tf32(v.z); r.w = f2tf32(v.w);
        reinterpret_cast<uint4*>(g_xr)[i] = r;
    }
    if (i < DD * N3D / 4) {
        float4 v = reinterpret_cast<const float4*>(W)[i];
        uint4 r;
        r.x = f2tf32(v.x); r.y = f2tf32(v.y);
        r.z = f2tf32(v.z); r.w = f2tf32(v.w);
        reinterpret_cast<uint4*>(g_wr)[i] = r;
    }
}

// ---------------------------------------------------------------------------
// Kernel 1: qkv = xr @ wr + b via TF32 mma.sync, cp.async 3-stage pipeline.
// Block tile 128(M) x 128(N), BK=16, 3 smem stages, 256 threads = 8 warps
// (2M x 4N), warp tile 64x32 = 4x4 m16n8k8 mmas, 2 k-steps per tile.
// Swizzles identical to the verified 2-stage version.
// Epilogue writes g_q/g_k/g_v RNA-rounded to tf32 (attention inputs).
// ---------------------------------------------------------------------------
__global__ __launch_bounds__(256, 2)
void qkv_mma_kernel(const float* __restrict__ bias) {
    __shared__ __align__(16) float sA[3][128 * 16];   // 8KB per stage
    __shared__ __align__(16) float sB[3][16 * 128];   // 8KB per stage

    const int tid  = threadIdx.x;
    const int lane = tid & 31;
    const int warp = tid >> 5;
    const int gid  = lane >> 2;
    const int tig  = lane & 3;
    const int warpM = (warp >> 2) * 64;
    const int warpN = (warp & 3) * 32;
    const int tileM = blockIdx.y * 128;
    const int tileN = blockIdx.x * 128;

    const int a_m0 = tid >> 2;
    const int a_kc = (tid & 3) * 4;
    const int b_k0 = tid >> 5;
    const int b_nc = (tid & 31) * 4;

    const uint32_t sAb = smem_u32(&sA[0][0]);
    const uint32_t sBb = smem_u32(&sB[0][0]);

    float acc[4][4][4];
#pragma unroll
    for (int mi = 0; mi < 4; mi++)
#pragma unroll
        for (int ni = 0; ni < 4; ni++)
#pragma unroll
            for (int c = 0; c < 4; c++) acc[mi][ni][c] = 0.0f;

#define ISSUE_TILE(t, s) do {                                                        \
        int _k0 = (t) * 16;                                                          \
        _Pragma("unroll")                                                            \
        for (int _i = 0; _i < 2; _i++) {                                             \
            int _m = a_m0 + _i * 64;                                                 \
            uint32_t _d = sAb + (uint32_t)((s) * 8192 +                              \
                          (_m * 16 + (a_kc ^ (4 * ((_m >> 1) & 3)))) * 4);           \
            cpasync16(_d, &g_xr[(size_t)(tileM + _m) * DD + _k0 + a_kc]);            \
        }                                                                            \
        _Pragma("unroll")                                                            \
        for (int _i = 0; _i < 2; _i++) {                                             \
            int _k = b_k0 + _i * 8;                                                  \
            uint32_t _d = sBb + (uint32_t)((s) * 8192 +                              \
                          (_k * 128 + (b_nc ^ (8 * (_k & 3)))) * 4);                 \
            cpasync16(_d, &g_wr[(size_t)(_k0 + _k) * N3D + tileN + b_nc]);           \
        }                                                                            \
        asm volatile("cp.async.commit_group;" ::: "memory");                         \
    } while (0)

    ISSUE_TILE(0, 0);
    ISSUE_TILE(1, 1);

    const int swzA = 4 * ((gid >> 1) & 3);
    const int NT = DD / 16;   // 64
    for (int t = 0; t < NT; t++) {
        // Keep 2 tiles in flight; ensure tile t's group has landed.
        if (t + 2 < NT) {
            ISSUE_TILE(t + 2, (t + 2) % 3);
            asm volatile("cp.async.wait_group 2;" ::: "memory");
        } else if (t + 1 < NT) {
            asm volatile("cp.async.wait_group 1;" ::: "memory");
        } else {
            asm volatile("cp.async.wait_group 0;" ::: "memory");
        }
        __syncthreads();

        const float* A  = &sA[t % 3][0];
        const float* Bt = &sB[t % 3][0];
#pragma unroll
        for (int ks = 0; ks < 16; ks += 8) {
            uint32_t af[4][4];
            uint32_t bf[4][2];
#pragma unroll
            for (int mi = 0; mi < 4; mi++) {
                int m0 = warpM + mi * 16 + gid;
                int kA = ks + tig;
                af[mi][0] = __float_as_uint(A[m0 * 16       + (kA ^ swzA)]);
                af[mi][1] = __float_as_uint(A[(m0 + 8) * 16 + (kA ^ swzA)]);
                af[mi][2] = __float_as_uint(A[m0 * 16       + ((kA + 4) ^ swzA)]);
                af[mi][3] = __float_as_uint(A[(m0 + 8) * 16 + ((kA + 4) ^ swzA)]);
            }
#pragma unroll
            for (int ni = 0; ni < 4; ni++) {
                int n0 = warpN + ni * 8 + gid;
                bf[ni][0] = __float_as_uint(Bt[(ks + tig) * 128     + (n0 ^ (8 * tig))]);
                bf[ni][1] = __float_as_uint(Bt[(ks + tig + 4) * 128 + (n0 ^ (8 * tig))]);
            }
#pragma unroll
            for (int mi = 0; mi < 4; mi++)
#pragma unroll
                for (int ni = 0; ni < 4; ni++)
                    mma_tf32(acc[mi][ni][0], acc[mi][ni][1], acc[mi][ni][2], acc[mi][ni][3],
                             af[mi][0], af[mi][1], af[mi][2], af[mi][3],
                             bf[ni][0], bf[ni][1]);
        }
        __syncthreads();   // all reads of stage t%3 done before it is re-issued
    }
#undef ISSUE_TILE

    // Epilogue: bias, then RNA-round to tf32 on store (attention operands).
#pragma unroll
    for (int mi = 0; mi < 4; mi++) {
#pragma unroll
        for (int ni = 0; ni < 4; ni++) {
            int row0 = tileM + warpM + mi * 16 + gid;
            int col0 = tileN + warpN + ni * 8 + tig * 2;
#pragma unroll
            for (int c = 0; c < 4; c++) {
                int m   = row0 + (c >> 1) * 8;
                int col = col0 + (c & 1);
                float val = acc[mi][ni][c] + bias[col];
                int b = m >> 10;
                int s = m & 1023;
                int h  = col / 192;
                int cc = col - h * 192;
                size_t base = ((size_t)(b * HH + h) * SS + s) * HD;
                if (cc < 64)       g_q[base + cc]       = f2tf32f(val * 0.125f);
                else if (cc < 128) g_k[base + cc - 64]  = f2tf32f(val);
                else               g_v[base + cc - 128] = f2tf32f(val);
            }
        }
    }
}

// ---------------------------------------------------------------------------
// Kernel 2: flash-attention via TF32 mma.sync (round-14 structure, 155us).
// Block = one (b,h) x 64 q-rows; 4 warps x 16 q-rows. 16 key tiles of 64.
// Q/K/V arrive already tf32-rounded from the GEMM epilogue; only P needs
// RNA rounding at its smem store.
//   SP: Qs then Ps [q][64], swizzle col ^ 4*(q&7)
//   Ks: [key][d],  swizzle d   ^ 4*(key&7)
//   Vs: [key][d],  swizzle d   ^ 8*(key&3)
// ---------------------------------------------------------------------------
__global__ __launch_bounds__(128)
void attn_mma_kernel(float* __restrict__ out) {
    __shared__ __align__(16) float SP[64 * 64];   // Qs, then reused as Ps
    __shared__ __align__(16) float Ks[64 * 64];
    __shared__ __align__(16) float Vs[64 * 64];

    const int tid  = threadIdx.x;
    const int lane = tid & 31;
    const int warp = tid >> 5;
    const int gid  = lane >> 2;      // 0..7
    const int tig  = lane & 3;       // 0..3
    const int m0   = warp * 16;
    const int bh   = blockIdx.x;     // 0..63
    const int q0   = blockIdx.y * 64;
    const int xq   = 4 * gid;

    const int sj = tid & 15;         // float4 within 64-float row
    const int sr = tid >> 4;         // + 8*p -> row 0..63

    // Stage Q (swizzled; already tf32-rounded in global)
#pragma unroll
    for (int p = 0; p < 8; p++) {
        int row = sr + 8 * p;
        float4 qv = *reinterpret_cast<const float4*>(
            &g_q[((size_t)bh * SS + q0 + row) * HD + 4 * sj]);
        *reinterpret_cast<float4*>(&SP[row * 64 + ((4 * sj) ^ (4 * (row & 7)))]) = qv;
    }
    __syncthreads();

    // Q fragments for all 8 k-steps, then SP is free for Ps
    uint32_t qf[8][4];
#pragma unroll
    for (int k8 = 0; k8 < 8; k8++) {
        int kk = k8 * 8;
        qf[k8][0] = __float_as_uint(SP[(m0 + gid) * 64     + ((kk + tig)     ^ xq)]);
        qf[k8][1] = __float_as_uint(SP[(m0 + gid + 8) * 64 + ((kk + tig)     ^ xq)]);
        qf[k8][2] = __float_as_uint(SP[(m0 + gid) * 64     + ((kk + tig + 4) ^ xq)]);
        qf[k8][3] = __float_as_uint(SP[(m0 + gid + 8) * 64 + ((kk + tig + 4) ^ xq)]);
    }

    float O[8][4];
#pragma unroll
    for (int nt = 0; nt < 8; nt++)
#pragma unroll
        for (int c = 0; c < 4; c++) O[nt][c] = 0.0f;
    float mA = -1e30f, mB = -1e30f, lA = 0.0f, lB = 0.0f;

    for (int kt = 0; kt < 16; kt++) {
        __syncthreads();   // prev PV done (and q-frags loaded, first iter)
        // Stage K and V tiles (swizzled; already tf32-rounded)
#pragma unroll
        for (int p = 0; p < 8; p++) {
            int row = sr + 8 * p;
            size_t gb = ((size_t)bh * SS + kt * 64 + row) * HD + 4 * sj;
            float4 kv = *reinterpret_cast<const float4*>(&g_k[gb]);
            float4 vv = *reinterpret_cast<const float4*>(&g_v[gb]);
            *reinterpret_cast<float4*>(&Ks[row * 64 + ((4 * sj) ^ (4 * (row & 7)))]) = kv;
            *reinterpret_cast<float4*>(&Vs[row * 64 + ((4 * sj) ^ (8 * (row & 3)))]) = vv;
        }
        __syncthreads();

        // --- S = Q @ K^T : B[k=d][n=key] = Ks[key][d] ---
        float sc[8][4];
#pragma unroll
        for (int nt = 0; nt < 8; nt++)
#pragma unroll
            for (int c = 0; c < 4; c++) sc[nt][c] = 0.0f;
#pragma unroll
        for (int k8 = 0; k8 < 8; k8++) {
            int kk = k8 * 8;
#pragma unroll
            for (int nt = 0; nt < 8; nt++) {
                int n0 = nt * 8;
                uint32_t b0 = __float_as_uint(Ks[(n0 + gid) * 64 + ((kk + tig)     ^ xq)]);
                uint32_t b1 = __float_as_uint(Ks[(n0 + gid) * 64 + ((kk + tig + 4) ^ xq)]);
                mma_tf32(sc[nt][0], sc[nt][1], sc[nt][2], sc[nt][3],
                         qf[k8][0], qf[k8][1], qf[k8][2], qf[k8][3], b0, b1);
            }
        }

        // --- online softmax (rows A=gid, B=gid+8) ---
        float tA = -1e30f, tB = -1e30f;
#pragma unroll
        for (int nt = 0; nt < 8; nt++) {
            tA = fmaxf(tA, fmaxf(sc[nt][0], sc[nt][1]));
            tB = fmaxf(tB, fmaxf(sc[nt][2], sc[nt][3]));
        }
        tA = fmaxf(tA, __shfl_xor_sync(0xffffffffu, tA, 1));
        tA = fmaxf(tA, __shfl_xor_sync(0xffffffffu, tA, 2));
        tB = fmaxf(tB, __shfl_xor_sync(0xffffffffu, tB, 1));
        tB = fmaxf(tB, __shfl_xor_sync(0xffffffffu, tB, 2));
        float mnA = fmaxf(mA, tA), mnB = fmaxf(mB, tB);
        float cA = __expf(mA - mnA), cB = __expf(mB - mnB);
        mA = mnA; mB = mnB;

        float psA = 0.0f, psB = 0.0f;
#pragma unroll
        for (int nt = 0; nt < 8; nt++) {
            float p0 = __expf(sc[nt][0] - mA);
            float p1 = __expf(sc[nt][1] - mA);
            float p2 = __expf(sc[nt][2] - mB);
            float p3 = __expf(sc[nt][3] - mB);
            psA += p0 + p1; psB += p2 + p3;
            int colw = (nt * 8 + 2 * tig) ^ xq;   // XOR(mult of 4) keeps float2 aligned
            *reinterpret_cast<float2*>(&SP[(m0 + gid) * 64 + colw]) =
                make_float2(f2tf32f(p0), f2tf32f(p1));
            *reinterpret_cast<float2*>(&SP[(m0 + gid + 8) * 64 + colw]) =
                make_float2(f2tf32f(p2), f2tf32f(p3));
            O[nt][0] *= cA; O[nt][1] *= cA; O[nt][2] *= cB; O[nt][3] *= cB;
        }
        psA += __shfl_xor_sync(0xffffffffu, psA, 1);
        psA += __shfl_xor_sync(0xffffffffu, psA, 2);
        psB += __shfl_xor_sync(0xffffffffu, psB, 1);
        psB += __shfl_xor_sync(0xffffffffu, psB, 2);
        lA = lA * cA + psA;
        lB = lB * cB + psB;
        __syncwarp();   // Ps visible to all lanes of this warp

        // --- O += P @ V : A = Ps (warp-private rows), B[k=key][n=d] = Vs ---
#pragma unroll
        for (int k8 = 0; k8 < 8; k8++) {
            int kk = k8 * 8;
            uint32_t a0 = __float_as_uint(SP[(m0 + gid) * 64     + ((kk + tig)     ^ xq)]);
            uint32_t a1 = __float_as_uint(SP[(m0 + gid + 8) * 64 + ((kk + tig)     ^ xq)]);
            uint32_t a2 = __float_as_uint(SP[(m0 + gid) * 64     + ((kk + tig + 4) ^ xq)]);
            uint32_t a3 = __float_as_uint(SP[(m0 + gid + 8) * 64 + ((kk + tig + 4) ^ xq)]);
#pragma unroll
            for (int nt = 0; nt < 8; nt++) {
                uint32_t b0 = __float_as_uint(Vs[(kk + tig) * 64     + ((nt * 8 + gid) ^ (8 * tig))]);
                uint32_t b1 = __float_as_uint(Vs[(kk + tig + 4) * 64 + ((nt * 8 + gid) ^ (8 * tig))]);
                mma_tf32(O[nt][0], O[nt][1], O[nt][2], O[nt][3], a0, a1, a2, a3, b0, b1);
            }
        }
    }

    // Epilogue: out[b, q, h*64 + d]
    const int b = bh >> 4;
    const int h = bh & 15;
    float iA = 1.0f / lA, iB = 1.0f / lB;
    size_t rowA = ((size_t)b * SS + q0 + m0 + gid) * DD + h * HD;
    size_t rowB = rowA + (size_t)8 * DD;
#pragma unroll
    for (int nt = 0; nt < 8; nt++) {
        int col = nt * 8 + 2 * tig;
        *reinterpret_cast<float2*>(&out[rowA + col]) = make_float2(O[nt][0] * iA, O[nt][1] * iA);
        *reinterpret_cast<float2*>(&out[rowB + col]) = make_float2(O[nt][2] * iB, O[nt][3] * iB);
    }
}

extern "C" void kernel_launch(void* const* d_in, const int* in_sizes, int n_in,
                              void* d_out, int out_size) {
    const float* x  = (const float*)d_in[0];   // [B,S,D]
    const float* Wq = (const float*)d_in[1];   // [D,3D]
    const float* bq = (const float*)d_in[2];   // [3D]
    float* out      = (float*)d_out;           // [B,S,D]

    int np = MM * DD / 4;
    preround_kernel<<<(np + 255) / 256, 256>>>(x, Wq);

    dim3 gridG(N3D / 128, MM / 128);           // (24, 32)
    qkv_mma_kernel<<<gridG, 256>>>(bq);

    dim3 gridA(BB * HH, SS / 64);              // (64, 16)
    attn_mma_kernel<<<gridA, 128>>>(out);
}